// round 1
// baseline (speedup 1.0000x reference)
#include <cuda_runtime.h>
#include <math.h>

// Problem constants
#define T_   4096
#define B_   32
#define I_   128
#define H_   128
#define TB_  (T_*B_)      // 131072 rows
#define G4_  (4*H_)       // 512 gate columns total

// Main-kernel tiling
#define MT  128           // rows per CTA
#define NT  128           // gate columns per CTA (32 heads x 4 gates)
#define KD  128           // full K staged once
#define LDA (KD+4)        // A smem row stride (floats), keeps 16B alignment
#define LDW (NT+4)        // W smem row stride

// Scratch (device globals -- no allocation allowed)
__device__ float g_hb[B_*G4_];          // Hb[b][g] = h0@W_hh^T + b_ih + b_hh
__device__ float g_warr[4*KD*NT];       // [ht][k][n], n = head_local*4 + gate

// ---------------- packed f32x2 helpers (Blackwell FFMA2 path) ----------------
#define PACK2(d, x, y) \
    asm("mov.b64 %0, {%1, %2};" : "=l"(d) : "r"(__float_as_uint(x)), "r"(__float_as_uint(y)))
#define UNPACK2(x, y, s) do { unsigned _lo, _hi; \
    asm("mov.b64 {%0, %1}, %2;" : "=r"(_lo), "=r"(_hi) : "l"(s)); \
    (x) = __uint_as_float(_lo); (y) = __uint_as_float(_hi); } while (0)
#define FMA2(accv, av, wv) \
    asm("fma.rn.f32x2 %0, %1, %2, %0;" : "+l"(accv) : "l"(av), "l"(wv))

// ---------------- prep: Hb = h0 @ W_hh^T + b_ih + b_hh ----------------
__global__ void prep_hb(const float* __restrict__ h0, const float* __restrict__ W_hh,
                        const float* __restrict__ b_ih, const float* __restrict__ b_hh) {
    int g = threadIdx.x;          // 0..511
    int b = blockIdx.x;           // 0..31
    float s = b_ih[g] + b_hh[g];
    const float* hr = h0 + b * H_;
    const float* wr = W_hh + g * H_;
#pragma unroll 8
    for (int k = 0; k < H_; k++) s += hr[k] * wr[k];
    g_hb[b * G4_ + g] = s;
}

// ---------------- prep: rearrange W_ih into [ht][k][n] gate-interleaved ----------------
// n = hl*4 + q  (hl = head within 32-head tile, q = gate 0..3)
// global gate row: g = q*128 + ht*32 + hl
__global__ void prep_w(const float* __restrict__ W_ih) {
    int idx = blockIdx.x * 256 + threadIdx.x;   // 0 .. 65535
    int ht  = idx >> 14;
    int rem = idx & 16383;
    int k   = rem >> 7;
    int n   = rem & 127;
    int q   = n & 3;
    int hl  = n >> 2;
    int g   = q * H_ + ht * 32 + hl;
    g_warr[idx] = W_ih[g * I_ + k];
}

// ---------------- main fused kernel ----------------
__global__ __launch_bounds__(256, 1)
void lstm_main(const float* __restrict__ input, const float* __restrict__ c0,
               const float* __restrict__ noise, float* __restrict__ out) {
    extern __shared__ float sm[];
    float* As  = sm;                       // MT*LDA   A tile, [m][k]
    float* Ws  = As + MT * LDA;            // KD*LDW   W tile, [k][n]
    float* HBs = Ws + KD * LDW;            // 32*128   Hb staged for this ht
    float* C0s = HBs + B_ * NT;            // 32*32
    float* NZs = C0s + B_ * 32;            // 32*32

    const int  tid = threadIdx.x;
    const int  ht  = blockIdx.x;                 // 0..3 head tile
    const long r0  = (long)blockIdx.y * MT;      // first row

    // --- stage A tile (coalesced float4, natural [m][k] layout) ---
    const float4* inp4 = (const float4*)(input + r0 * I_);
#pragma unroll
    for (int it = 0; it < 16; it++) {
        int idx = tid + it * 256;            // m*32 + kq
        int m = idx >> 5, kq = idx & 31;
        float4 v = inp4[idx];
        *(float4*)(As + m * LDA + kq * 4) = v;
    }
    // --- stage W tile (already [k][n] in g_warr, coalesced) ---
    const float4* w4 = (const float4*)(g_warr + ht * (KD * NT));
#pragma unroll
    for (int it = 0; it < 16; it++) {
        int idx = tid + it * 256;            // k*32 + nq
        int k = idx >> 5, nq = idx & 31;
        float4 v = w4[idx];
        *(float4*)(Ws + k * LDW + nq * 4) = v;
    }
    // --- stage Hb for this head tile: HBs[b][n] ---
#pragma unroll
    for (int it = 0; it < 16; it++) {
        int idx = tid + it * 256;            // b*128 + n
        int b = idx >> 7, n = idx & 127;
        int g = (n & 3) * H_ + ht * 32 + (n >> 2);
        HBs[idx] = g_hb[b * G4_ + g];
    }
    // --- stage c0/noise slices: [b][hl] for hl in this head tile ---
#pragma unroll
    for (int it = 0; it < 4; it++) {
        int idx = tid + it * 256;            // b*32 + hl
        int b = idx >> 5, hl = idx & 31;
        C0s[idx] = c0[b * H_ + ht * 32 + hl];
        NZs[idx] = noise[b * H_ + ht * 32 + hl];
    }
    __syncthreads();

    const int tx = tid & 15, ty = tid >> 4;      // 16 x 16 thread grid
    const float* Ab = As + (ty * 8) * LDA;
    const float* Wb = Ws + tx * 8;

    unsigned long long acc[8][4];                // 8 rows x 4 col-pairs (packed f32x2)
#pragma unroll
    for (int i = 0; i < 8; i++)
#pragma unroll
        for (int p = 0; p < 4; p++) acc[i][p] = 0ull;

#pragma unroll 4
    for (int k = 0; k < KD; k += 2) {
        float2 a[8];
#pragma unroll
        for (int i = 0; i < 8; i++) a[i] = *(const float2*)(Ab + i * LDA + k);
        float4 w0a = *(const float4*)(Wb + k * LDW);
        float4 w0b = *(const float4*)(Wb + k * LDW + 4);
        float4 w1a = *(const float4*)(Wb + (k + 1) * LDW);
        float4 w1b = *(const float4*)(Wb + (k + 1) * LDW + 4);
        unsigned long long w0[4], w1[4];
        PACK2(w0[0], w0a.x, w0a.y); PACK2(w0[1], w0a.z, w0a.w);
        PACK2(w0[2], w0b.x, w0b.y); PACK2(w0[3], w0b.z, w0b.w);
        PACK2(w1[0], w1a.x, w1a.y); PACK2(w1[1], w1a.z, w1a.w);
        PACK2(w1[2], w1b.x, w1b.y); PACK2(w1[3], w1b.z, w1b.w);
#pragma unroll
        for (int i = 0; i < 8; i++) {
            unsigned long long a0, a1;
            PACK2(a0, a[i].x, a[i].x);
            PACK2(a1, a[i].y, a[i].y);
            FMA2(acc[i][0], a0, w0[0]);
            FMA2(acc[i][1], a0, w0[1]);
            FMA2(acc[i][2], a0, w0[2]);
            FMA2(acc[i][3], a0, w0[3]);
            FMA2(acc[i][0], a1, w1[0]);
            FMA2(acc[i][1], a1, w1[1]);
            FMA2(acc[i][2], a1, w1[2]);
            FMA2(acc[i][3], a1, w1[3]);
        }
    }

    // --- fused LSTM-cell epilogue ---
    const int nb = tx * 8;                   // first gate-col of this thread
#pragma unroll
    for (int i = 0; i < 8; i++) {
        long r = r0 + ty * 8 + i;
        int  b = (int)(r & (B_ - 1));        // row r = t*B + b
        float v[8];
#pragma unroll
        for (int p = 0; p < 4; p++) UNPACK2(v[2 * p], v[2 * p + 1], acc[i][p]);
        float hv[2], cv[2];
#pragma unroll
        for (int hh = 0; hh < 2; hh++) {
            const float* hb = HBs + b * NT + nb + hh * 4;
            float gi = v[hh * 4 + 0] + hb[0];
            float gf = v[hh * 4 + 1] + hb[1];
            float gg = v[hh * 4 + 2] + hb[2];
            float go = v[hh * 4 + 3] + hb[3];
            float si = 1.f / (1.f + expf(-gi));
            float sf = 1.f / (1.f + expf(-gf));
            float tg = tanhf(gg);
            float so = 1.f / (1.f + expf(-go));
            int hl = tx * 2 + hh;
            float c = sf * C0s[b * 32 + hl] + si * tg;
            cv[hh] = c;
            hv[hh] = so * tanhf(c) + NZs[b * 32 + hl];
        }
        float2 hp = make_float2(hv[0], hv[1]);
        long obase = r * H_ + ht * 32 + tx * 2;
        *(float2*)(out + obase) = hp;
        if (r >= (long)TB_ - B_) {           // last timestep: also h_last, c_last
            long lb = (long)TB_ * H_ + (long)b * H_ + ht * 32 + tx * 2;
            *(float2*)(out + lb) = hp;
            *(float2*)(out + lb + B_ * H_) = make_float2(cv[0], cv[1]);
        }
    }
}

// ---------------- launch ----------------
extern "C" void kernel_launch(void* const* d_in, const int* in_sizes, int n_in,
                              void* d_out, int out_size) {
    const float* input = (const float*)d_in[0];
    const float* h0    = (const float*)d_in[1];
    const float* c0    = (const float*)d_in[2];
    const float* noise = (const float*)d_in[3];
    const float* W_ih  = (const float*)d_in[4];
    const float* W_hh  = (const float*)d_in[5];
    const float* b_ih  = (const float*)d_in[6];
    const float* b_hh  = (const float*)d_in[7];
    float* out = (float*)d_out;

    prep_hb<<<B_, G4_>>>(h0, W_hh, b_ih, b_hh);
    prep_w<<<256, 256>>>(W_ih);

    const int smem = (MT * LDA + KD * LDW + B_ * NT + B_ * 32 + B_ * 32) * (int)sizeof(float);
    cudaFuncSetAttribute(lstm_main, cudaFuncAttributeMaxDynamicSharedMemorySize, smem);

    dim3 grid(4, TB_ / MT);   // 4 head tiles x 1024 row tiles
    lstm_main<<<grid, 256, smem>>>(input, c0, noise, out);
}